// round 15
// baseline (speedup 1.0000x reference)
#include <cuda_runtime.h>
#include <cuda_fp16.h>
#include <math.h>
#include <stdint.h>

#define NB 8
#define TT 2048
#define DD 1024
#define MTOT (NB*TT)

#define BM 128
#define BKE 32
#define STAGES 4
#define NTHR 128

// stage = 8K (A single fp16) + 2*GN*1024 (B hi+lo)
#define STGB(GN)   (8192 + 2*(GN)*1024)
#define SMEMSZ(GN) (STAGES*STGB(GN))
#define SMEM_QKV   SMEMSZ(8)     // 98304; x2 CTAs = 192K <= 227K
#define SMEM_SC    SMEMSZ(8)
#define SMEM_AV    SMEMSZ(4)

__device__ __half g_x[(size_t)MTOT*DD];                         // x: single fp16
__device__ __half g_wqhi[DD*DD], g_wqlo[DD*DD];
__device__ __half g_wkhi[DD*DD], g_wklo[DD*DD];
__device__ __half g_wvhi[DD*DD], g_wvlo[DD*DD];
__device__ __half g_qhi[(size_t)MTOT*DD];                       // q: single fp16
__device__ __half g_khi[(size_t)MTOT*DD], g_klo[(size_t)MTOT*DD];
__device__ __half g_vthi[(size_t)MTOT*DD], g_vtlo[(size_t)MTOT*DD];  // [DD][MTOT]
__device__ __half g_ahi[(size_t)NB*TT*TT];                      // attn: single fp16
__device__ float g_sc[(size_t)NB*TT*TT];
__device__ float g_temp[MTOT];

// ------------------------- helpers -------------------------
__device__ __forceinline__ uint32_t smem_u32(const void* p) {
    uint32_t a;
    asm("{ .reg .u64 t; cvta.to.shared.u64 t, %1; cvt.u32.u64 %0, t; }" : "=r"(a) : "l"(p));
    return a;
}
__device__ __forceinline__ void cp16(uint32_t dst, const void* src) {
    asm volatile("cp.async.cg.shared.global [%0], [%1], 16;" :: "r"(dst), "l"(src));
}
__device__ __forceinline__ void ldsm4(uint32_t* r, uint32_t a) {
    asm volatile("ldmatrix.sync.aligned.m8n8.x4.shared.b16 {%0,%1,%2,%3}, [%4];"
                 : "=r"(r[0]), "=r"(r[1]), "=r"(r[2]), "=r"(r[3]) : "r"(a));
}
__device__ __forceinline__ void mma_f16(float* c, const uint32_t* a, const uint32_t* b) {
    asm volatile("mma.sync.aligned.m16n8k16.row.col.f32.f16.f16.f32 "
                 "{%0,%1,%2,%3}, {%4,%5,%6,%7}, {%8,%9}, {%0,%1,%2,%3};"
                 : "+f"(c[0]), "+f"(c[1]), "+f"(c[2]), "+f"(c[3])
                 : "r"(a[0]), "r"(a[1]), "r"(a[2]), "r"(a[3]), "r"(b[0]), "r"(b[1]));
}
// 16B-chunk XOR swizzle: row r, chunk c (0..3); 64B rows
__device__ __forceinline__ uint32_t swoff(int r, int c) {
    return (uint32_t)((r * 4 + (c ^ ((r >> 1) & 3))) << 4);
}
__device__ __forceinline__ uint32_t pack2h(__half a, __half b) {
    __half2 t(a, b);
    return *(uint32_t*)&t;
}
__device__ __forceinline__ void split1h(float f, __half& h, __half& l) {
    h = __float2half(f);
    l = __float2half(f - __half2float(h));
}
__device__ __forceinline__ float warp_sum(float v) {
#pragma unroll
    for (int o = 16; o > 0; o >>= 1) v += __shfl_xor_sync(0xffffffffu, v, o);
    return v;
}
__device__ __forceinline__ float warp_max(float v) {
#pragma unroll
    for (int o = 16; o > 0; o >>= 1) v = fmaxf(v, __shfl_xor_sync(0xffffffffu, v, o));
    return v;
}

// ---------------------------------------------------------------------------
// Core fp16 2-term HMMA mainloop: acc += A_hi*(B_hi+B_lo)^T.
// Tile BM x 16*GN, 4 warps (2x2), 4 stages, 2 CTAs/SM, cp.async interleaved.
// ---------------------------------------------------------------------------
template <int GN>
__device__ __forceinline__ void gemm_core(
    const __half* __restrict__ Ahi,
    const __half* __restrict__ Bhi, const __half* __restrict__ Blo,
    int K, int lda, int ldb, int m0, int n0,
    uint32_t sbase, int tid, float acc[4][GN][4])
{
    constexpr int ABY   = 8192;
    constexpr int BLOFF = ABY + GN * 1024;
    constexpr int STG   = STGB(GN);
    const int lane = tid & 31, wid = tid >> 5;
    const int wm = wid >> 1, wn = wid & 1;
    const int KT = K / BKE;

    const int rA = (lane & 7) + ((lane >> 3) & 1) * 8;
    const int cA = lane >> 4;
    const int rB = (lane & 7) + ((lane >> 4) & 1) * 8;
    const int cB = (lane >> 3) & 1;

    auto load_A = [&](int kt) {
        const uint32_t st = sbase + (uint32_t)(kt % STAGES) * STG;
        const int k0 = kt * BKE;
#pragma unroll
        for (int i = 0; i < 4; i++) {
            const int id = tid + i * NTHR;
            const int r = id >> 2, c = id & 3;
            cp16(st + swoff(r, c), Ahi + (size_t)(m0 + r) * lda + k0 + c * 8);
        }
    };
    auto load_B = [&](int kt) {
        const uint32_t st = sbase + (uint32_t)(kt % STAGES) * STG;
        const int k0 = kt * BKE;
#pragma unroll
        for (int i = 0; i < GN / 2; i++) {
            const int id = tid + i * NTHR;
            const int r = id >> 2, c = id & 3;
            const uint32_t so = swoff(r, c);
            const size_t gb = (size_t)(n0 + r) * ldb + k0 + c * 8;
            cp16(st + ABY + so,   Bhi + gb);
            cp16(st + BLOFF + so, Blo + gb);
        }
        asm volatile("cp.async.commit_group;");
    };

    // prologue: 3 stages in flight
    load_A(0); load_B(0);
    load_A(1); load_B(1);
    load_A(2); load_B(2);

    for (int kt = 0; kt < KT; kt++) {
        if (kt == KT - 1)      asm volatile("cp.async.wait_group 0;");
        else if (kt == KT - 2) asm volatile("cp.async.wait_group 1;");
        else                   asm volatile("cp.async.wait_group 2;");
        __syncthreads();
        const bool more = (kt + 3 < KT);

        const uint32_t st = sbase + (uint32_t)(kt % STAGES) * STG;
#pragma unroll
        for (int k16 = 0; k16 < 2; k16++) {
            uint32_t bh[GN * 2], bl[GN * 2];
#pragma unroll
            for (int g2 = 0; g2 < GN / 2; g2++) {
                const int r = wn * (GN * 8) + g2 * 16 + rB;
                const uint32_t ad = st + ABY + swoff(r, k16 * 2 + cB);
                ldsm4(&bh[g2 * 4], ad);
                ldsm4(&bl[g2 * 4], ad + GN * 1024);
            }
            if (more) {
                if (k16 == 0) load_A(kt + 3);
                else          load_B(kt + 3);
            }
#pragma unroll
            for (int f = 0; f < 4; f++) {
                uint32_t ah[4];
                const int r = wm * 64 + f * 16 + rA;
                ldsm4(ah, st + swoff(r, k16 * 2 + cA));
#pragma unroll
                for (int g = 0; g < GN; g++) {
                    mma_f16(acc[f][g], ah, &bh[g * 2]);
                    mma_f16(acc[f][g], ah, &bl[g * 2]);
                }
            }
        }
    }
}

// ---------------------------------------------------------------------------
// q/k projection (fp16 2-term, GN=8): z=0 -> q (fp16 single),
// z=1 -> k (fp16 hi/lo).
// ---------------------------------------------------------------------------
__global__ __launch_bounds__(NTHR, 2)
void qk_kernel(const __half* __restrict__ x,
               const __half* __restrict__ wqh, const __half* __restrict__ wql,
               const __half* __restrict__ wkh, const __half* __restrict__ wkl,
               __half* __restrict__ qhi,
               __half* __restrict__ khi, __half* __restrict__ klo)
{
    extern __shared__ char sm[];
    const uint32_t sbase = smem_u32(sm);
    const int tid = threadIdx.x, lane = tid & 31, wid = tid >> 5;
    const int wm = wid >> 1, wn = wid & 1;
    const int m0 = blockIdx.y * BM, n0 = blockIdx.x * 128, z = blockIdx.z;

    const __half* Bh = (z == 0) ? wqh : wkh;
    const __half* Bl = (z == 0) ? wql : wkl;

    float acc[4][8][4];
#pragma unroll
    for (int f = 0; f < 4; f++)
#pragma unroll
        for (int g = 0; g < 8; g++)
#pragma unroll
            for (int p = 0; p < 4; p++) acc[f][g][p] = 0.0f;

    gemm_core<8>(x, Bh, Bl, DD, DD, DD, m0, n0, sbase, tid, acc);

    if (z == 0) {
#pragma unroll
        for (int f = 0; f < 4; f++) {
            const int r1 = m0 + wm * 64 + f * 16 + (lane >> 2);
            const int r2 = r1 + 8;
#pragma unroll
            for (int g = 0; g < 8; g++) {
                const int col = n0 + wn * 64 + g * 8 + (lane & 3) * 2;
                *(uint32_t*)(qhi + (size_t)r1 * DD + col) =
                    pack2h(__float2half(acc[f][g][0]), __float2half(acc[f][g][1]));
                *(uint32_t*)(qhi + (size_t)r2 * DD + col) =
                    pack2h(__float2half(acc[f][g][2]), __float2half(acc[f][g][3]));
            }
        }
    } else {
#pragma unroll
        for (int f = 0; f < 4; f++) {
            const int r1 = m0 + wm * 64 + f * 16 + (lane >> 2);
            const int r2 = r1 + 8;
#pragma unroll
            for (int g = 0; g < 8; g++) {
                const int col = n0 + wn * 64 + g * 8 + (lane & 3) * 2;
                __half h0, l0, h1, l1;
                split1h(acc[f][g][0], h0, l0); split1h(acc[f][g][1], h1, l1);
                *(uint32_t*)(khi + (size_t)r1 * DD + col) = pack2h(h0, h1);
                *(uint32_t*)(klo + (size_t)r1 * DD + col) = pack2h(l0, l1);
                split1h(acc[f][g][2], h0, l0); split1h(acc[f][g][3], h1, l1);
                *(uint32_t*)(khi + (size_t)r2 * DD + col) = pack2h(h0, h1);
                *(uint32_t*)(klo + (size_t)r2 * DD + col) = pack2h(l0, l1);
            }
        }
    }
}

// ---------------------------------------------------------------------------
// v projection (fp16 2-term, GN=8): out transposed [e][token] fp16 hi/lo.
// Runs on a forked stream, overlapped with qk/temp/scores/softmax.
// ---------------------------------------------------------------------------
__global__ __launch_bounds__(NTHR, 2)
void v_kernel(const __half* __restrict__ x,
              const __half* __restrict__ wvh, const __half* __restrict__ wvl,
              __half* __restrict__ vth, __half* __restrict__ vtl)
{
    extern __shared__ char sm[];
    const uint32_t sbase = smem_u32(sm);
    const int tid = threadIdx.x, lane = tid & 31, wid = tid >> 5;
    const int wm = wid >> 1, wn = wid & 1;
    const int m0 = blockIdx.y * BM, n0 = blockIdx.x * 128;

    float acc[4][8][4];
#pragma unroll
    for (int f = 0; f < 4; f++)
#pragma unroll
        for (int g = 0; g < 8; g++)
#pragma unroll
            for (int p = 0; p < 4; p++) acc[f][g][p] = 0.0f;

    gemm_core<8>(x, wvh, wvl, DD, DD, DD, m0, n0, sbase, tid, acc);

    __syncthreads();    // stage buffers reused for transpose
    float* ws = (float*)sm + (size_t)wid * (64 * 65);   // [64][65] per warp
#pragma unroll
    for (int f = 0; f < 4; f++)
#pragma unroll
        for (int g = 0; g < 8; g++) {
            const int mm = f * 16 + (lane >> 2);
            const int nn = g * 8 + (lane & 3) * 2;
            ws[mm * 65 + nn]           = acc[f][g][0];
            ws[mm * 65 + nn + 1]       = acc[f][g][1];
            ws[(mm + 8) * 65 + nn]     = acc[f][g][2];
            ws[(mm + 8) * 65 + nn + 1] = acc[f][g][3];
        }
    __syncwarp();
#pragma unroll
    for (int half_ = 0; half_ < 2; half_++) {
        const int nloc = lane + half_ * 32;
        const int nrow = n0 + wn * 64 + nloc;
        uint32_t* ph = (uint32_t*)(vth + (size_t)nrow * MTOT + m0 + wm * 64);
        uint32_t* pl = (uint32_t*)(vtl + (size_t)nrow * MTOT + m0 + wm * 64);
#pragma unroll
        for (int mq = 0; mq < 32; mq++) {
            __half h0, l0, h1, l1;
            split1h(ws[(2 * mq) * 65 + nloc],     h0, l0);
            split1h(ws[(2 * mq + 1) * 65 + nloc], h1, l1);
            ph[mq] = pack2h(h0, h1);
            pl[mq] = pack2h(l0, l1);
        }
    }
}

// ---------------------------------------------------------------------------
// fp16 2-term batched GEMM.  MODE 2: C fp32 * rowscale[row]; MODE 3: C fp32.
// ---------------------------------------------------------------------------
template <int MODE, int GN>
__global__ __launch_bounds__(NTHR, 2)
void gemm2_kernel(const __half* __restrict__ Ahi,
                  const __half* __restrict__ Bhi, const __half* __restrict__ Blo,
                  float* __restrict__ Cf,
                  int K, int lda, int ldb, int ldc,
                  size_t sA, size_t sB, size_t sC, const float* __restrict__ rowscale)
{
    extern __shared__ char sm[];
    const uint32_t sbase = smem_u32(sm);
    const int tid = threadIdx.x, lane = tid & 31, wid = tid >> 5;
    const int wm = wid >> 1, wn = wid & 1;
    const int m0 = blockIdx.y * BM, n0 = blockIdx.x * (16 * GN), z = blockIdx.z;

    float acc[4][GN][4];
#pragma unroll
    for (int f = 0; f < 4; f++)
#pragma unroll
        for (int g = 0; g < GN; g++)
#pragma unroll
            for (int p = 0; p < 4; p++) acc[f][g][p] = 0.0f;

    gemm_core<GN>(Ahi + (size_t)z * sA,
                  Bhi + (size_t)z * sB, Blo + (size_t)z * sB,
                  K, lda, ldb, m0, n0, sbase, tid, acc);

    float* C0 = Cf + (size_t)z * sC;
#pragma unroll
    for (int f = 0; f < 4; f++) {
        const int r1 = m0 + wm * 64 + f * 16 + (lane >> 2);
        const int r2 = r1 + 8;
        float s1 = 1.0f, s2 = 1.0f;
        if (MODE == 2) {
            s1 = rowscale[(size_t)z * TT + r1];
            s2 = rowscale[(size_t)z * TT + r2];
        }
#pragma unroll
        for (int g = 0; g < GN; g++) {
            const int col = n0 + wn * (GN * 8) + g * 8 + (lane & 3) * 2;
            *(float2*)(C0 + (size_t)r1 * ldc + col) = make_float2(acc[f][g][0] * s1, acc[f][g][1] * s1);
            *(float2*)(C0 + (size_t)r2 * ldc + col) = make_float2(acc[f][g][2] * s2, acc[f][g][3] * s2);
        }
    }
}

// ------------------------- aux kernels -------------------------
__global__ void splitX_kernel(const float* __restrict__ x, __half* __restrict__ out, size_t n4)
{
    size_t i = (size_t)blockIdx.x * blockDim.x + threadIdx.x;
    if (i >= n4) return;
    float4 v = ((const float4*)x)[i];
    ((uint2*)out)[i] = make_uint2(pack2h(__float2half(v.x), __float2half(v.y)),
                                  pack2h(__float2half(v.z), __float2half(v.w)));
}

__global__ void splitW_kernel(const float* __restrict__ Wq, const float* __restrict__ Wk,
                              const float* __restrict__ Wv,
                              __half* __restrict__ qh, __half* __restrict__ ql,
                              __half* __restrict__ kh, __half* __restrict__ kl,
                              __half* __restrict__ vh, __half* __restrict__ vl)
{
    const int z = blockIdx.y;
    const float* src = (z == 0) ? Wq : (z == 1) ? Wk : Wv;
    __half* hi = (z == 0) ? qh : (z == 1) ? kh : vh;
    __half* lo = (z == 0) ? ql : (z == 1) ? kl : vl;
    size_t i = (size_t)blockIdx.x * blockDim.x + threadIdx.x;
    float4 v = ((const float4*)src)[i];
    __half h0,l0,h1,l1,h2,l2,h3,l3;
    split1h(v.x,h0,l0); split1h(v.y,h1,l1); split1h(v.z,h2,l2); split1h(v.w,h3,l3);
    ((uint2*)hi)[i] = make_uint2(pack2h(h0,h1), pack2h(h2,h3));
    ((uint2*)lo)[i] = make_uint2(pack2h(l0,l1), pack2h(l2,l3));
}

// warp-per-row temp: block 256 = 8 rows
__global__ void temp_kernel(const __half* __restrict__ qhi,
                            const float* __restrict__ hbar, float* __restrict__ temp)
{
    const int wid = threadIdx.x >> 5, lane = threadIdx.x & 31;
    const int row = blockIdx.x * 8 + wid;
    const __half* p = qhi + (size_t)row * DD;
    float s = 0.0f;
#pragma unroll
    for (int j = 0; j < 4; j++) {
        uint4 u = *(const uint4*)(p + j * 256 + lane * 8);
        const __half2* hp = (const __half2*)&u;
#pragma unroll
        for (int q = 0; q < 4; q++) {
            float2 f = __half22float2(hp[q]);
            s += f.x * f.x + f.y * f.y;
        }
    }
    s = warp_sum(s);
    if (lane == 0) {
        float tv = hbar[0] / (sqrtf(s) + 1e-8f);
        temp[row] = fminf(fmaxf(tv, 0.1f), 5.0f);
    }
}

// warp-per-row softmax: block 256 = 8 rows; 64 elems/lane in registers
__global__ void softmax_kernel(const float* __restrict__ sc, __half* __restrict__ ahi)
{
    const int wid = threadIdx.x >> 5, lane = threadIdx.x & 31;
    const size_t row = (size_t)blockIdx.x * 8 + wid;
    const float* p = sc + row * (size_t)TT;

    float v[64];
    float mx = -3.4e38f;
#pragma unroll
    for (int j = 0; j < 16; j++) {
        float4 a = *(const float4*)(p + j * 128 + lane * 4);
        v[j*4]   = a.x; v[j*4+1] = a.y; v[j*4+2] = a.z; v[j*4+3] = a.w;
        mx = fmaxf(mx, fmaxf(fmaxf(a.x, a.y), fmaxf(a.z, a.w)));
    }
    mx = warp_max(mx);
    float s = 0.0f;
#pragma unroll
    for (int j = 0; j < 64; j++) { v[j] = __expf(v[j] - mx); s += v[j]; }
    s = warp_sum(s);
    const float inv = 1.0f / s;

    __half* o = ahi + row * (size_t)TT;
#pragma unroll
    for (int j = 0; j < 16; j++) {
        uint2 w = make_uint2(
            pack2h(__float2half(v[j*4]   * inv), __float2half(v[j*4+1] * inv)),
            pack2h(__float2half(v[j*4+2] * inv), __float2half(v[j*4+3] * inv)));
        *(uint2*)(o + j * 128 + lane * 4) = w;
    }
}

// ---------------------------------------------------------------------------
extern "C" void kernel_launch(void* const* d_in, const int* in_sizes, int n_in,
                              void* d_out, int out_size)
{
    const float* x  = (const float*)d_in[0];
    const float* Wq = (const float*)d_in[1];
    const float* Wk = (const float*)d_in[2];
    const float* Wv = (const float*)d_in[3];
    const float* hb = (const float*)d_in[4];
    float* out = (float*)d_out;

    __half *xh,*wqh,*wql,*wkh,*wkl,*wvh,*wvl,*qhi,*khi,*klo,*vth,*vtl,*ahi;
    float *sc, *tmp;
    cudaGetSymbolAddress((void**)&xh,  g_x);
    cudaGetSymbolAddress((void**)&wqh, g_wqhi); cudaGetSymbolAddress((void**)&wql, g_wqlo);
    cudaGetSymbolAddress((void**)&wkh, g_wkhi); cudaGetSymbolAddress((void**)&wkl, g_wklo);
    cudaGetSymbolAddress((void**)&wvh, g_wvhi); cudaGetSymbolAddress((void**)&wvl, g_wvlo);
    cudaGetSymbolAddress((void**)&qhi, g_qhi);
    cudaGetSymbolAddress((void**)&khi, g_khi);  cudaGetSymbolAddress((void**)&klo, g_klo);
    cudaGetSymbolAddress((void**)&vth, g_vthi); cudaGetSymbolAddress((void**)&vtl, g_vtlo);
    cudaGetSymbolAddress((void**)&ahi, g_ahi);
    cudaGetSymbolAddress((void**)&sc,  g_sc);   cudaGetSymbolAddress((void**)&tmp, g_temp);

    cudaFuncSetAttribute(qk_kernel,           cudaFuncAttributeMaxDynamicSharedMemorySize, SMEM_QKV);
    cudaFuncSetAttribute(v_kernel,            cudaFuncAttributeMaxDynamicSharedMemorySize, SMEM_QKV);
    cudaFuncSetAttribute((gemm2_kernel<2,8>), cudaFuncAttributeMaxDynamicSharedMemorySize, SMEM_SC);
    cudaFuncSetAttribute((gemm2_kernel<3,4>), cudaFuncAttributeMaxDynamicSharedMemorySize, SMEM_AV);

    // lazy-init side stream + events (host objects; no device allocation)
    static cudaStream_t s2 = nullptr;
    static cudaEvent_t evFork = nullptr, evJoin = nullptr;
    if (!s2) {
        cudaStreamCreate(&s2);
        cudaEventCreateWithFlags(&evFork, cudaEventDisableTiming);
        cudaEventCreateWithFlags(&evJoin, cudaEventDisableTiming);
    }

    // 1) splits: x single fp16; W fp16 hi/lo (merged)
    splitX_kernel<<<(size_t)MTOT*DD/4/256, 256>>>(x, xh, (size_t)MTOT*DD/4);
    {
        dim3 gw(DD*DD/4/256, 3);
        splitW_kernel<<<gw, 256>>>(Wq, Wk, Wv, wqh, wql, wkh, wkl, wvh, wvl);
    }

    // fork: v projection on side stream, overlapped with qk/temp/scores/softmax
    cudaEventRecord(evFork, 0);
    cudaStreamWaitEvent(s2, evFork, 0);
    {
        dim3 gv(DD/128, MTOT/BM, 1);
        v_kernel<<<gv, NTHR, SMEM_QKV, s2>>>(xh, wvh, wvl, vth, vtl);
    }
    cudaEventRecord(evJoin, s2);

    // 2) q/k projections (main stream)
    dim3 gqk(DD/128, MTOT/BM, 2);
    qk_kernel<<<gqk, NTHR, SMEM_QKV>>>(xh, wqh, wql, wkh, wkl, qhi, khi, klo);

    // 3) temp from q (warp-per-row)
    temp_kernel<<<MTOT/8, 256>>>(qhi, hb, tmp);

    // 4) scores = (q@k^T) * temp   fp16 2-term, BN=128
    dim3 gs(TT/128, TT/BM, NB);
    gemm2_kernel<2,8><<<gs, NTHR, SMEM_SC>>>(qhi, khi, klo, sc,
                                             DD, DD, DD, TT,
                                             (size_t)TT*DD, (size_t)TT*DD, (size_t)TT*TT, tmp);

    // 5) softmax -> attn fp16 single (warp-per-row)
    softmax_kernel<<<MTOT/8, 256>>>(sc, ahi);

    // join: AV needs v projection done
    cudaStreamWaitEvent(0, evJoin, 0);

    // 6) out = attn @ v   fp16 2-term, BN=64
    dim3 go(DD/64, TT/BM, NB);
    gemm2_kernel<3,4><<<go, NTHR, SMEM_AV>>>(ahi, vth, vtl, out,
                                             TT, TT, MTOT, DD,
                                             (size_t)TT*TT, TT, (size_t)TT*DD, nullptr);
}

// round 16
// speedup vs baseline: 1.0039x; 1.0039x over previous
#include <cuda_runtime.h>
#include <cuda_fp16.h>
#include <math.h>
#include <stdint.h>

#define NB 8
#define TT 2048
#define DD 1024
#define MTOT (NB*TT)

#define BM 128
#define BKE 64
#define STAGES 2
#define NTHR 128

// stage = 16K (A single fp16, 128x64) + 2*GN*2048 (B hi+lo, 16GN x 64)
#define STGB(GN)   (16384 + (GN)*4096)
#define SMEMSZ(GN) (STAGES*STGB(GN))
#define SMEM_QKV   SMEMSZ(8)     // 98304; x2 CTAs = 192K <= 227K
#define SMEM_SC    SMEMSZ(8)
#define SMEM_AV    SMEMSZ(4)

__device__ __half g_x[(size_t)MTOT*DD];                         // x: single fp16
__device__ __half g_wqhi[DD*DD], g_wqlo[DD*DD];
__device__ __half g_wkhi[DD*DD], g_wklo[DD*DD];
__device__ __half g_wvhi[DD*DD], g_wvlo[DD*DD];
__device__ __half g_qhi[(size_t)MTOT*DD];                       // q: single fp16
__device__ __half g_khi[(size_t)MTOT*DD], g_klo[(size_t)MTOT*DD];
__device__ __half g_vthi[(size_t)MTOT*DD], g_vtlo[(size_t)MTOT*DD];  // [DD][MTOT]
__device__ __half g_ahi[(size_t)NB*TT*TT];                      // attn: single fp16
__device__ float g_sc[(size_t)NB*TT*TT];
__device__ float g_temp[MTOT];

// ------------------------- helpers -------------------------
__device__ __forceinline__ uint32_t smem_u32(const void* p) {
    uint32_t a;
    asm("{ .reg .u64 t; cvta.to.shared.u64 t, %1; cvt.u32.u64 %0, t; }" : "=r"(a) : "l"(p));
    return a;
}
__device__ __forceinline__ void cp16(uint32_t dst, const void* src) {
    asm volatile("cp.async.cg.shared.global [%0], [%1], 16;" :: "r"(dst), "l"(src));
}
__device__ __forceinline__ void ldsm4(uint32_t* r, uint32_t a) {
    asm volatile("ldmatrix.sync.aligned.m8n8.x4.shared.b16 {%0,%1,%2,%3}, [%4];"
                 : "=r"(r[0]), "=r"(r[1]), "=r"(r[2]), "=r"(r[3]) : "r"(a));
}
__device__ __forceinline__ void mma_f16(float* c, const uint32_t* a, const uint32_t* b) {
    asm volatile("mma.sync.aligned.m16n8k16.row.col.f32.f16.f16.f32 "
                 "{%0,%1,%2,%3}, {%4,%5,%6,%7}, {%8,%9}, {%0,%1,%2,%3};"
                 : "+f"(c[0]), "+f"(c[1]), "+f"(c[2]), "+f"(c[3])
                 : "r"(a[0]), "r"(a[1]), "r"(a[2]), "r"(a[3]), "r"(b[0]), "r"(b[1]));
}
// full SW128 swizzle: 128B rows, 8 chunks of 16B; chunk ^= row&7
__device__ __forceinline__ uint32_t swoff(int r, int c) {
    return (uint32_t)((r * 8 + (c ^ (r & 7))) << 4);
}
__device__ __forceinline__ uint32_t pack2h(__half a, __half b) {
    __half2 t(a, b);
    return *(uint32_t*)&t;
}
__device__ __forceinline__ void split1h(float f, __half& h, __half& l) {
    h = __float2half(f);
    l = __float2half(f - __half2float(h));
}
__device__ __forceinline__ float warp_sum(float v) {
#pragma unroll
    for (int o = 16; o > 0; o >>= 1) v += __shfl_xor_sync(0xffffffffu, v, o);
    return v;
}
__device__ __forceinline__ float warp_max(float v) {
#pragma unroll
    for (int o = 16; o > 0; o >>= 1) v = fmaxf(v, __shfl_xor_sync(0xffffffffu, v, o));
    return v;
}

// ---------------------------------------------------------------------------
// Core fp16 2-term HMMA mainloop, BKE=64, 2 stages.
// acc += A_hi*(B_hi+B_lo)^T.  Tile BM x 16*GN, 4 warps (2x2), 2 CTAs/SM.
// One __syncthreads per 64 K-elements; next-stage loads interleaved.
// ---------------------------------------------------------------------------
template <int GN>
__device__ __forceinline__ void gemm_core(
    const __half* __restrict__ Ahi,
    const __half* __restrict__ Bhi, const __half* __restrict__ Blo,
    int K, int lda, int ldb, int m0, int n0,
    uint32_t sbase, int tid, float acc[4][GN][4])
{
    constexpr int ABY   = 16384;
    constexpr int BLOFF = ABY + GN * 2048;
    constexpr int STG   = STGB(GN);
    const int lane = tid & 31, wid = tid >> 5;
    const int wm = wid >> 1, wn = wid & 1;
    const int KT = K / BKE;

    const int rA = (lane & 7) + ((lane >> 3) & 1) * 8;
    const int cA = lane >> 4;               // k-half chunk within k16
    const int rB = (lane & 7) + ((lane >> 4) & 1) * 8;
    const int cB = (lane >> 3) & 1;

    auto load_A = [&](int kt) {
        const uint32_t st = sbase + (uint32_t)(kt & 1) * STG;
        const int k0 = kt * BKE;
#pragma unroll
        for (int i = 0; i < 8; i++) {       // 128 rows x 8 chunks
            const int id = tid + i * NTHR;
            const int r = id >> 3, c = id & 7;
            cp16(st + swoff(r, c), Ahi + (size_t)(m0 + r) * lda + k0 + c * 8);
        }
    };
    auto load_Bhi = [&](int kt) {
        const uint32_t st = sbase + (uint32_t)(kt & 1) * STG;
        const int k0 = kt * BKE;
#pragma unroll
        for (int i = 0; i < GN; i++) {      // 16*GN rows x 8 chunks
            const int id = tid + i * NTHR;
            const int r = id >> 3, c = id & 7;
            cp16(st + ABY + swoff(r, c), Bhi + (size_t)(n0 + r) * ldb + k0 + c * 8);
        }
    };
    auto load_Blo = [&](int kt) {
        const uint32_t st = sbase + (uint32_t)(kt & 1) * STG;
        const int k0 = kt * BKE;
#pragma unroll
        for (int i = 0; i < GN; i++) {
            const int id = tid + i * NTHR;
            const int r = id >> 3, c = id & 7;
            cp16(st + BLOFF + swoff(r, c), Blo + (size_t)(n0 + r) * ldb + k0 + c * 8);
        }
        asm volatile("cp.async.commit_group;");
    };

    load_A(0); load_Bhi(0); load_Blo(0);

    for (int kt = 0; kt < KT; kt++) {
        asm volatile("cp.async.wait_group 0;");
        __syncthreads();
        const bool more = (kt + 1 < KT);

        const uint32_t st = sbase + (uint32_t)(kt & 1) * STG;
#pragma unroll
        for (int k16 = 0; k16 < 4; k16++) {
            uint32_t bh[GN * 2], bl[GN * 2];
#pragma unroll
            for (int g2 = 0; g2 < GN / 2; g2++) {
                const int r = wn * (GN * 8) + g2 * 16 + rB;
                const int ch = k16 * 2 + cB;
                ldsm4(&bh[g2 * 4], st + ABY + swoff(r, ch));
                ldsm4(&bl[g2 * 4], st + BLOFF + swoff(r, ch));
            }
            if (more) {
                if (k16 == 0)      load_A(kt + 1);
                else if (k16 == 1) load_Bhi(kt + 1);
                else if (k16 == 2) load_Blo(kt + 1);   // + commit
            }
#pragma unroll
            for (int f = 0; f < 4; f++) {
                uint32_t ah[4];
                const int r = wm * 64 + f * 16 + rA;
                ldsm4(ah, st + swoff(r, k16 * 2 + cA));
#pragma unroll
                for (int g = 0; g < GN; g++) {
                    mma_f16(acc[f][g], ah, &bh[g * 2]);
                    mma_f16(acc[f][g], ah, &bl[g * 2]);
                }
            }
        }
    }
}

// ---------------------------------------------------------------------------
// Merged QKV projection (fp16 2-term, GN=8): z=0 -> q (fp16 single),
// z=1 -> k (fp16 hi/lo), z=2 -> v transposed [e][token] (fp16 hi/lo).
// ---------------------------------------------------------------------------
__global__ __launch_bounds__(NTHR, 2)
void qkv_kernel(const __half* __restrict__ x,
                const __half* __restrict__ wqh, const __half* __restrict__ wql,
                const __half* __restrict__ wkh, const __half* __restrict__ wkl,
                const __half* __restrict__ wvh, const __half* __restrict__ wvl,
                __half* __restrict__ qhi,
                __half* __restrict__ khi, __half* __restrict__ klo,
                __half* __restrict__ vth, __half* __restrict__ vtl)
{
    extern __shared__ char sm[];
    const uint32_t sbase = smem_u32(sm);
    const int tid = threadIdx.x, lane = tid & 31, wid = tid >> 5;
    const int wm = wid >> 1, wn = wid & 1;
    const int m0 = blockIdx.y * BM, n0 = blockIdx.x * 128, z = blockIdx.z;

    const __half* Bh = (z == 0) ? wqh : (z == 1) ? wkh : wvh;
    const __half* Bl = (z == 0) ? wql : (z == 1) ? wkl : wvl;

    float acc[4][8][4];
#pragma unroll
    for (int f = 0; f < 4; f++)
#pragma unroll
        for (int g = 0; g < 8; g++)
#pragma unroll
            for (int p = 0; p < 4; p++) acc[f][g][p] = 0.0f;

    gemm_core<8>(x, Bh, Bl, DD, DD, DD, m0, n0, sbase, tid, acc);

    if (z == 0) {
#pragma unroll
        for (int f = 0; f < 4; f++) {
            const int r1 = m0 + wm * 64 + f * 16 + (lane >> 2);
            const int r2 = r1 + 8;
#pragma unroll
            for (int g = 0; g < 8; g++) {
                const int col = n0 + wn * 64 + g * 8 + (lane & 3) * 2;
                *(uint32_t*)(qhi + (size_t)r1 * DD + col) =
                    pack2h(__float2half(acc[f][g][0]), __float2half(acc[f][g][1]));
                *(uint32_t*)(qhi + (size_t)r2 * DD + col) =
                    pack2h(__float2half(acc[f][g][2]), __float2half(acc[f][g][3]));
            }
        }
    } else if (z == 1) {
#pragma unroll
        for (int f = 0; f < 4; f++) {
            const int r1 = m0 + wm * 64 + f * 16 + (lane >> 2);
            const int r2 = r1 + 8;
#pragma unroll
            for (int g = 0; g < 8; g++) {
                const int col = n0 + wn * 64 + g * 8 + (lane & 3) * 2;
                __half h0, l0, h1, l1;
                split1h(acc[f][g][0], h0, l0); split1h(acc[f][g][1], h1, l1);
                *(uint32_t*)(khi + (size_t)r1 * DD + col) = pack2h(h0, h1);
                *(uint32_t*)(klo + (size_t)r1 * DD + col) = pack2h(l0, l1);
                split1h(acc[f][g][2], h0, l0); split1h(acc[f][g][3], h1, l1);
                *(uint32_t*)(khi + (size_t)r2 * DD + col) = pack2h(h0, h1);
                *(uint32_t*)(klo + (size_t)r2 * DD + col) = pack2h(l0, l1);
            }
        }
    } else {
        __syncthreads();    // stage buffers reused for transpose
        float* ws = (float*)sm + (size_t)wid * (64 * 65);   // [64][65] per warp
#pragma unroll
        for (int f = 0; f < 4; f++)
#pragma unroll
            for (int g = 0; g < 8; g++) {
                const int mm = f * 16 + (lane >> 2);
                const int nn = g * 8 + (lane & 3) * 2;
                ws[mm * 65 + nn]           = acc[f][g][0];
                ws[mm * 65 + nn + 1]       = acc[f][g][1];
                ws[(mm + 8) * 65 + nn]     = acc[f][g][2];
                ws[(mm + 8) * 65 + nn + 1] = acc[f][g][3];
            }
        __syncwarp();
#pragma unroll
        for (int half_ = 0; half_ < 2; half_++) {
            const int nloc = lane + half_ * 32;
            const int nrow = n0 + wn * 64 + nloc;
            uint32_t* ph = (uint32_t*)(vth + (size_t)nrow * MTOT + m0 + wm * 64);
            uint32_t* pl = (uint32_t*)(vtl + (size_t)nrow * MTOT + m0 + wm * 64);
#pragma unroll
            for (int mq = 0; mq < 32; mq++) {
                __half h0, l0, h1, l1;
                split1h(ws[(2 * mq) * 65 + nloc],     h0, l0);
                split1h(ws[(2 * mq + 1) * 65 + nloc], h1, l1);
                ph[mq] = pack2h(h0, h1);
                pl[mq] = pack2h(l0, l1);
            }
        }
    }
}

// ---------------------------------------------------------------------------
// fp16 2-term batched GEMM.  MODE 2: C fp32 * rowscale[row]; MODE 3: C fp32.
// ---------------------------------------------------------------------------
template <int MODE, int GN>
__global__ __launch_bounds__(NTHR, 2)
void gemm2_kernel(const __half* __restrict__ Ahi,
                  const __half* __restrict__ Bhi, const __half* __restrict__ Blo,
                  float* __restrict__ Cf,
                  int K, int lda, int ldb, int ldc,
                  size_t sA, size_t sB, size_t sC, const float* __restrict__ rowscale)
{
    extern __shared__ char sm[];
    const uint32_t sbase = smem_u32(sm);
    const int tid = threadIdx.x, lane = tid & 31, wid = tid >> 5;
    const int wm = wid >> 1, wn = wid & 1;
    const int m0 = blockIdx.y * BM, n0 = blockIdx.x * (16 * GN), z = blockIdx.z;

    float acc[4][GN][4];
#pragma unroll
    for (int f = 0; f < 4; f++)
#pragma unroll
        for (int g = 0; g < GN; g++)
#pragma unroll
            for (int p = 0; p < 4; p++) acc[f][g][p] = 0.0f;

    gemm_core<GN>(Ahi + (size_t)z * sA,
                  Bhi + (size_t)z * sB, Blo + (size_t)z * sB,
                  K, lda, ldb, m0, n0, sbase, tid, acc);

    float* C0 = Cf + (size_t)z * sC;
#pragma unroll
    for (int f = 0; f < 4; f++) {
        const int r1 = m0 + wm * 64 + f * 16 + (lane >> 2);
        const int r2 = r1 + 8;
        float s1 = 1.0f, s2 = 1.0f;
        if (MODE == 2) {
            s1 = rowscale[(size_t)z * TT + r1];
            s2 = rowscale[(size_t)z * TT + r2];
        }
#pragma unroll
        for (int g = 0; g < GN; g++) {
            const int col = n0 + wn * (GN * 8) + g * 8 + (lane & 3) * 2;
            *(float2*)(C0 + (size_t)r1 * ldc + col) = make_float2(acc[f][g][0] * s1, acc[f][g][1] * s1);
            *(float2*)(C0 + (size_t)r2 * ldc + col) = make_float2(acc[f][g][2] * s2, acc[f][g][3] * s2);
        }
    }
}

// ------------------------- aux kernels -------------------------
__global__ void splitX_kernel(const float* __restrict__ x, __half* __restrict__ out, size_t n4)
{
    size_t i = (size_t)blockIdx.x * blockDim.x + threadIdx.x;
    if (i >= n4) return;
    float4 v = ((const float4*)x)[i];
    ((uint2*)out)[i] = make_uint2(pack2h(__float2half(v.x), __float2half(v.y)),
                                  pack2h(__float2half(v.z), __float2half(v.w)));
}

__global__ void splitW_kernel(const float* __restrict__ Wq, const float* __restrict__ Wk,
                              const float* __restrict__ Wv,
                              __half* __restrict__ qh, __half* __restrict__ ql,
                              __half* __restrict__ kh, __half* __restrict__ kl,
                              __half* __restrict__ vh, __half* __restrict__ vl)
{
    const int z = blockIdx.y;
    const float* src = (z == 0) ? Wq : (z == 1) ? Wk : Wv;
    __half* hi = (z == 0) ? qh : (z == 1) ? kh : vh;
    __half* lo = (z == 0) ? ql : (z == 1) ? kl : vl;
    size_t i = (size_t)blockIdx.x * blockDim.x + threadIdx.x;
    float4 v = ((const float4*)src)[i];
    __half h0,l0,h1,l1,h2,l2,h3,l3;
    split1h(v.x,h0,l0); split1h(v.y,h1,l1); split1h(v.z,h2,l2); split1h(v.w,h3,l3);
    ((uint2*)hi)[i] = make_uint2(pack2h(h0,h1), pack2h(h2,h3));
    ((uint2*)lo)[i] = make_uint2(pack2h(l0,l1), pack2h(l2,l3));
}

// warp-per-row temp: block 256 = 8 rows
__global__ void temp_kernel(const __half* __restrict__ qhi,
                            const float* __restrict__ hbar, float* __restrict__ temp)
{
    const int wid = threadIdx.x >> 5, lane = threadIdx.x & 31;
    const int row = blockIdx.x * 8 + wid;
    const __half* p = qhi + (size_t)row * DD;
    float s = 0.0f;
#pragma unroll
    for (int j = 0; j < 4; j++) {
        uint4 u = *(const uint4*)(p + j * 256 + lane * 8);
        const __half2* hp = (const __half2*)&u;
#pragma unroll
        for (int q = 0; q < 4; q++) {
            float2 f = __half22float2(hp[q]);
            s += f.x * f.x + f.y * f.y;
        }
    }
    s = warp_sum(s);
    if (lane == 0) {
        float tv = hbar[0] / (sqrtf(s) + 1e-8f);
        temp[row] = fminf(fmaxf(tv, 0.1f), 5.0f);
    }
}

// warp-per-row softmax: block 256 = 8 rows; 64 elems/lane in registers
__global__ void softmax_kernel(const float* __restrict__ sc, __half* __restrict__ ahi)
{
    const int wid = threadIdx.x >> 5, lane = threadIdx.x & 31;
    const size_t row = (size_t)blockIdx.x * 8 + wid;
    const float* p = sc + row * (size_t)TT;

    float v[64];
    float mx = -3.4e38f;
#pragma unroll
    for (int j = 0; j < 16; j++) {
        float4 a = *(const float4*)(p + j * 128 + lane * 4);
        v[j*4]   = a.x; v[j*4+1] = a.y; v[j*4+2] = a.z; v[j*4+3] = a.w;
        mx = fmaxf(mx, fmaxf(fmaxf(a.x, a.y), fmaxf(a.z, a.w)));
    }
    mx = warp_max(mx);
    float s = 0.0f;
#pragma unroll
    for (int j = 0; j < 64; j++) { v[j] = __expf(v[j] - mx); s += v[j]; }
    s = warp_sum(s);
    const float inv = 1.0f / s;

    __half* o = ahi + row * (size_t)TT;
#pragma unroll
    for (int j = 0; j < 16; j++) {
        uint2 w = make_uint2(
            pack2h(__float2half(v[j*4]   * inv), __float2half(v[j*4+1] * inv)),
            pack2h(__float2half(v[j*4+2] * inv), __float2half(v[j*4+3] * inv)));
        *(uint2*)(o + j * 128 + lane * 4) = w;
    }
}

// ---------------------------------------------------------------------------
extern "C" void kernel_launch(void* const* d_in, const int* in_sizes, int n_in,
                              void* d_out, int out_size)
{
    const float* x  = (const float*)d_in[0];
    const float* Wq = (const float*)d_in[1];
    const float* Wk = (const float*)d_in[2];
    const float* Wv = (const float*)d_in[3];
    const float* hb = (const float*)d_in[4];
    float* out = (float*)d_out;

    __half *xh,*wqh,*wql,*wkh,*wkl,*wvh,*wvl,*qhi,*khi,*klo,*vth,*vtl,*ahi;
    float *sc, *tmp;
    cudaGetSymbolAddress((void**)&xh,  g_x);
    cudaGetSymbolAddress((void**)&wqh, g_wqhi); cudaGetSymbolAddress((void**)&wql, g_wqlo);
    cudaGetSymbolAddress((void**)&wkh, g_wkhi); cudaGetSymbolAddress((void**)&wkl, g_wklo);
    cudaGetSymbolAddress((void**)&wvh, g_wvhi); cudaGetSymbolAddress((void**)&wvl, g_wvlo);
    cudaGetSymbolAddress((void**)&qhi, g_qhi);
    cudaGetSymbolAddress((void**)&khi, g_khi);  cudaGetSymbolAddress((void**)&klo, g_klo);
    cudaGetSymbolAddress((void**)&vth, g_vthi); cudaGetSymbolAddress((void**)&vtl, g_vtlo);
    cudaGetSymbolAddress((void**)&ahi, g_ahi);
    cudaGetSymbolAddress((void**)&sc,  g_sc);   cudaGetSymbolAddress((void**)&tmp, g_temp);

    cudaFuncSetAttribute(qkv_kernel,          cudaFuncAttributeMaxDynamicSharedMemorySize, SMEM_QKV);
    cudaFuncSetAttribute((gemm2_kernel<2,8>), cudaFuncAttributeMaxDynamicSharedMemorySize, SMEM_SC);
    cudaFuncSetAttribute((gemm2_kernel<3,4>), cudaFuncAttributeMaxDynamicSharedMemorySize, SMEM_AV);

    // 1) splits: x single fp16; W fp16 hi/lo (merged)
    splitX_kernel<<<(size_t)MTOT*DD/4/256, 256>>>(x, xh, (size_t)MTOT*DD/4);
    {
        dim3 gw(DD*DD/4/256, 3);
        splitW_kernel<<<gw, 256>>>(Wq, Wk, Wv, wqh, wql, wkh, wkl, wvh, wvl);
    }

    // 2) merged q/k/v projections (fp16 2-term)
    dim3 gq(DD/128, MTOT/BM, 3);
    qkv_kernel<<<gq, NTHR, SMEM_QKV>>>(xh, wqh, wql, wkh, wkl, wvh, wvl,
                                       qhi, khi, klo, vth, vtl);

    // 3) temp from q (warp-per-row)
    temp_kernel<<<MTOT/8, 256>>>(qhi, hb, tmp);

    // 4) scores = (q@k^T) * temp   fp16 2-term, BN=128
    dim3 gs(TT/128, TT/BM, NB);
    gemm2_kernel<2,8><<<gs, NTHR, SMEM_SC>>>(qhi, khi, klo, sc,
                                             DD, DD, DD, TT,
                                             (size_t)TT*DD, (size_t)TT*DD, (size_t)TT*TT, tmp);

    // 5) softmax -> attn fp16 single (warp-per-row)
    softmax_kernel<<<MTOT/8, 256>>>(sc, ahi);

    // 6) out = attn @ v   fp16 2-term, BN=64
    dim3 go(DD/64, TT/BM, NB);
    gemm2_kernel<3,4><<<go, NTHR, SMEM_AV>>>(ahi, vth, vtl, out,
                                             TT, TT, MTOT, DD,
                                             (size_t)TT*TT, TT, (size_t)TT*DD, nullptr);
}